// round 7
// baseline (speedup 1.0000x reference)
#include <cuda_runtime.h>
#include <cuda_bf16.h>
#include <cstdint>

// Problem constants
#define B_    8
#define N_    1024
#define FIN   256
#define NH    8
#define ND    32
#define M_TOT (B_ * N_)      // 8192
#define NBH   (B_ * NH)      // 64
#define OCOLS (NH * ND)      // 256

// ---------------- scratch ----------------
__device__ float g_buf[M_TOT * OCOLS];        // g[m][h*32+d] fp32
__device__ float ssrc_buf[NBH * N_];          // [bh][n]
__device__ float sdst_buf[NBH * N_];          // [bh][n]
__device__ int   sid_buf[NBH * N_];
__device__ float e1_buf[NBH * N_];            // exp(v_k) at sorted position k
__device__ float e2_buf[NBH * N_];            // exp(0.2 v_k)
__device__ float cb1_buf[NBH * 32 * 32];      // [bh][chunk][d]: inclusive-suffix base
__device__ float cb2_buf[NBH * 32 * 32];      // [bh][chunk][d]: exclusive-prefix base
__device__ float4 qscal_buf[NBH * N_];        // [bh][n]: {E1/den, E2/den, -, -}
__device__ uint32_t qlist_buf[NBH * N_];      // [bh][slot]: i | (r<<10), bucketed by chunk
__device__ int cstart_buf[NBH * 33];          // bucket starts

// ---------------- mma.sync helper ----------------
#define MMA_BF16(d, a, b)                                                      \
    asm volatile("mma.sync.aligned.m16n8k16.row.col.f32.bf16.bf16.f32 "        \
        "{%0,%1,%2,%3}, {%4,%5,%6,%7}, {%8,%9}, {%0,%1,%2,%3};"                \
        : "+f"((d)[0]), "+f"((d)[1]), "+f"((d)[2]), "+f"((d)[3])               \
        : "r"((a)[0]), "r"((a)[1]), "r"((a)[2]), "r"((a)[3]),                  \
          "r"((b)[0]), "r"((b)[1]))

// ---------------- kernel 1: g = vertex @ w_vert via HMMA bf16 hi/lo,
//                  fused s_src/s_dst epilogue, reg-prefetch pipeline ----------------
#define KC 32
#define APAD 8
__global__ __launch_bounds__(256) void gemm_mma_k(const float* __restrict__ A,
                                                  const float* __restrict__ W,
                                                  const float* __restrict__ attn_w) {
    __shared__ __align__(16) __nv_bfloat16 Ah[64][KC + APAD];
    __shared__ __align__(16) __nv_bfloat16 Al[64][KC + APAD];
    __shared__ __align__(16) __nv_bfloat16 Bh[128][KC + APAD];
    __shared__ __align__(16) __nv_bfloat16 Bl[128][KC + APAD];

    const int tid = threadIdx.x;
    const int wid = tid >> 5, lane = tid & 31;
    const int wm = wid >> 2, wn = wid & 3;
    const int rowBase = blockIdx.y * 64;
    const int colBase = blockIdx.x * 128;
    const int g = lane >> 2, tg = lane & 3;

    const int ar0 = tid >> 3, ac4 = (tid & 7) << 2;
    const int ar1 = (tid + 256) >> 3;
    const int bk0 = tid >> 5, bn4 = (tid & 31) << 2;

    float acc[2][4][4];
#pragma unroll
    for (int mt = 0; mt < 2; mt++)
#pragma unroll
        for (int nt = 0; nt < 4; nt++)
#pragma unroll
            for (int r = 0; r < 4; r++) acc[mt][nt][r] = 0.f;

    float4 pa[2], pb[4];
    pa[0] = *(const float4*)(A + (size_t)(rowBase + ar0) * FIN + ac4);
    pa[1] = *(const float4*)(A + (size_t)(rowBase + ar1) * FIN + ac4);
#pragma unroll
    for (int it = 0; it < 4; it++)
        pb[it] = *(const float4*)(W + (size_t)(bk0 + it * 8) * OCOLS + colBase + bn4);

    for (int kc = 0; kc < 8; kc++) {
        __syncthreads();
#pragma unroll
        for (int it = 0; it < 2; it++) {
            int r = (it == 0) ? ar0 : ar1;
            float xs[4] = {pa[it].x, pa[it].y, pa[it].z, pa[it].w};
#pragma unroll
            for (int c = 0; c < 4; c++) {
                __nv_bfloat16 h = __float2bfloat16(xs[c]);
                Ah[r][ac4 + c] = h;
                Al[r][ac4 + c] = __float2bfloat16(xs[c] - __bfloat162float(h));
            }
        }
#pragma unroll
        for (int it = 0; it < 4; it++) {
            int kr = bk0 + it * 8;
            float xs[4] = {pb[it].x, pb[it].y, pb[it].z, pb[it].w};
#pragma unroll
            for (int c = 0; c < 4; c++) {
                __nv_bfloat16 h = __float2bfloat16(xs[c]);
                Bh[bn4 + c][kr] = h;
                Bl[bn4 + c][kr] = __float2bfloat16(xs[c] - __bfloat162float(h));
            }
        }
        __syncthreads();

        if (kc < 7) {
            int k0 = (kc + 1) * KC;
            pa[0] = *(const float4*)(A + (size_t)(rowBase + ar0) * FIN + k0 + ac4);
            pa[1] = *(const float4*)(A + (size_t)(rowBase + ar1) * FIN + k0 + ac4);
#pragma unroll
            for (int it = 0; it < 4; it++)
                pb[it] = *(const float4*)(W + (size_t)(k0 + bk0 + it * 8) * OCOLS + colBase + bn4);
        }

#pragma unroll
        for (int ks = 0; ks < 2; ks++) {
            const int kk = ks << 4;
            uint32_t ah[2][4], al[2][4], bb[4][2];
#pragma unroll
            for (int mt = 0; mt < 2; mt++) {
                int r0 = wm * 32 + mt * 16 + g;
                ah[mt][0] = *(const uint32_t*)&Ah[r0][kk + tg * 2];
                ah[mt][1] = *(const uint32_t*)&Ah[r0 + 8][kk + tg * 2];
                ah[mt][2] = *(const uint32_t*)&Ah[r0][kk + 8 + tg * 2];
                ah[mt][3] = *(const uint32_t*)&Ah[r0 + 8][kk + 8 + tg * 2];
                al[mt][0] = *(const uint32_t*)&Al[r0][kk + tg * 2];
                al[mt][1] = *(const uint32_t*)&Al[r0 + 8][kk + tg * 2];
                al[mt][2] = *(const uint32_t*)&Al[r0][kk + 8 + tg * 2];
                al[mt][3] = *(const uint32_t*)&Al[r0 + 8][kk + 8 + tg * 2];
            }
#pragma unroll
            for (int nt = 0; nt < 4; nt++) {
                int n0 = wn * 32 + nt * 8 + g;
                bb[nt][0] = *(const uint32_t*)&Bh[n0][kk + tg * 2];
                bb[nt][1] = *(const uint32_t*)&Bh[n0][kk + 8 + tg * 2];
            }
#pragma unroll
            for (int mt = 0; mt < 2; mt++)
#pragma unroll
                for (int nt = 0; nt < 4; nt++) {
                    MMA_BF16(acc[mt][nt], ah[mt], bb[nt]);
                    MMA_BF16(acc[mt][nt], al[mt], bb[nt]);
                }
#pragma unroll
            for (int nt = 0; nt < 4; nt++) {
                int n0 = wn * 32 + nt * 8 + g;
                bb[nt][0] = *(const uint32_t*)&Bl[n0][kk + tg * 2];
                bb[nt][1] = *(const uint32_t*)&Bl[n0][kk + 8 + tg * 2];
            }
#pragma unroll
            for (int mt = 0; mt < 2; mt++)
#pragma unroll
                for (int nt = 0; nt < 4; nt++)
                    MMA_BF16(acc[mt][nt], ah[mt], bb[nt]);
        }
    }

#pragma unroll
    for (int mt = 0; mt < 2; mt++) {
        int r0 = rowBase + wm * 32 + mt * 16 + g;
#pragma unroll
        for (int nt = 0; nt < 4; nt++) {
            int c0 = colBase + wn * 32 + nt * 8 + tg * 2;
            *(float2*)(g_buf + (size_t)r0 * OCOLS + c0) =
                make_float2(acc[mt][nt][0], acc[mt][nt][1]);
            *(float2*)(g_buf + (size_t)(r0 + 8) * OCOLS + c0) =
                make_float2(acc[mt][nt][2], acc[mt][nt][3]);
        }
    }

    // fused score
    {
        float ws[4][2], wd[4][2];
#pragma unroll
        for (int nt = 0; nt < 4; nt++)
#pragma unroll
            for (int j = 0; j < 2; j++) {
                int d = nt * 8 + tg * 2 + j;
                ws[nt][j] = attn_w[d];
                wd[nt][j] = attn_w[32 + d];
            }
        int hh = blockIdx.x * 4 + wn;
#pragma unroll
        for (int mt = 0; mt < 2; mt++)
#pragma unroll
            for (int rh = 0; rh < 2; rh++) {
                float as = 0.f, ad = 0.f;
#pragma unroll
                for (int nt = 0; nt < 4; nt++) {
                    as += acc[mt][nt][rh * 2] * ws[nt][0] + acc[mt][nt][rh * 2 + 1] * ws[nt][1];
                    ad += acc[mt][nt][rh * 2] * wd[nt][0] + acc[mt][nt][rh * 2 + 1] * wd[nt][1];
                }
                as += __shfl_xor_sync(0xffffffffu, as, 1);
                as += __shfl_xor_sync(0xffffffffu, as, 2);
                ad += __shfl_xor_sync(0xffffffffu, ad, 1);
                ad += __shfl_xor_sync(0xffffffffu, ad, 2);
                if (tg == 0) {
                    int m = rowBase + wm * 32 + mt * 16 + rh * 8 + g;
                    int b = m >> 10, i = m & 1023;
                    ssrc_buf[(size_t)(b * NH + hh) * N_ + i] = as;
                    sdst_buf[(size_t)(b * NH + hh) * N_ + i] = ad;
                }
            }
    }
}

// ---------------- kernel 2: sort + scans + query scalars + binning + chunk bases ----------------
__device__ __forceinline__ void warp_passes_u(uint32_t& key, int k, int jmax, int tid) {
    for (int j = jmax; j > 0; j >>= 1) {
        uint32_t pk = __shfl_xor_sync(0xffffffffu, key, j);
        bool lower = ((tid & j) == 0);
        bool up = ((tid & k) == 0);
        bool keepmin = (lower == up);
        bool sw = keepmin ? (key > pk) : (key < pk);
        if (sw) key = pk;
    }
}

__global__ __launch_bounds__(1024) void prep_k() {
    __shared__ uint32_t su[1024];
    __shared__ float vs[1024];
    __shared__ float e1s[1024];
    __shared__ float e2s[1024];
    __shared__ float sc1[1025];
    __shared__ float sc2[1025];
    __shared__ float wt[32], wo[32], wt2[32], wo2[32];
    __shared__ float tot1[32][33];
    __shared__ float tot2[32][33];
    __shared__ int bcnt[32], boff[32];

    int bh = blockIdx.x;
    int b = bh >> 3, h = bh & 7;
    int tid = threadIdx.x;
    int w = tid >> 5, lane = tid & 31;

    if (tid < 32) bcnt[tid] = 0;

    float v0 = sdst_buf[(size_t)bh * N_ + tid];
    uint32_t u = __float_as_uint(v0);
    u = (u & 0x80000000u) ? ~u : (u | 0x80000000u);   // order-preserving
    uint32_t key = (u & 0xFFFFFC00u) | (uint32_t)tid;

#pragma unroll
    for (int k = 2; k <= 32; k <<= 1) warp_passes_u(key, k, k >> 1, tid);
    su[tid] = key;
    __syncthreads();
    for (int k = 64; k <= 1024; k <<= 1) {
        for (int j = k >> 1; j >= 32; j >>= 1) {
            int ixj = tid ^ j;
            if (ixj > tid) {
                bool up = ((tid & k) == 0);
                uint32_t a = su[tid], c = su[ixj];
                bool sw = up ? (a > c) : (a < c);
                if (sw) { su[tid] = c; su[ixj] = a; }
            }
            __syncthreads();
        }
        key = su[tid];
        warp_passes_u(key, k, 16, tid);
        su[tid] = key;
        __syncthreads();
    }

    int idj = (int)(key & 1023u);
    float rv = sdst_buf[(size_t)bh * N_ + idj];       // exact value
    vs[tid] = rv;
    sid_buf[(size_t)bh * N_ + tid] = idj;
    float x1 = __expf(rv);
    float x2 = __expf(0.2f * rv);
    e1s[tid] = x1; e2s[tid] = x2;
    e1_buf[(size_t)bh * N_ + tid] = x1;
    e2_buf[(size_t)bh * N_ + tid] = x2;

    // scalar scans (c1: suffix of e1; c2: prefix of e2)
    float s2 = x2;
#pragma unroll
    for (int o = 1; o < 32; o <<= 1) {
        float y = __shfl_up_sync(0xffffffffu, s2, o);
        if (lane >= o) s2 += y;
    }
    if (lane == 31) wt2[w] = s2;
    float s1 = x1;
#pragma unroll
    for (int o = 1; o < 32; o <<= 1) {
        float y = __shfl_down_sync(0xffffffffu, s1, o);
        if (lane + o < 32) s1 += y;
    }
    if (lane == 0) wt[w] = s1;
    __syncthreads();
    if (w == 0) {
        float t = wt[lane];
        float ts = t;
#pragma unroll
        for (int o = 1; o < 32; o <<= 1) {
            float y = __shfl_down_sync(0xffffffffu, ts, o);
            if (lane + o < 32) ts += y;
        }
        wo[lane] = ts - t;
        float t2 = wt2[lane];
        float ps = t2;
#pragma unroll
        for (int o = 1; o < 32; o <<= 1) {
            float y = __shfl_up_sync(0xffffffffu, ps, o);
            if (lane >= o) ps += y;
        }
        wo2[lane] = ps - t2;
    }
    __syncthreads();
    sc1[tid] = s1 + wo[w];
    sc2[tid + 1] = s2 + wo2[w];
    if (tid == 0) {
        sc1[1024] = 0.f;
        sc2[0] = 0.f;
    }
    __syncthreads();

    // ---- per-query scalars + chunk binning ----
    {
        float src = ssrc_buf[(size_t)bh * N_ + tid];
        float th = -src;
        int lo = 0, hi = 1024;
#pragma unroll
        for (int s = 0; s < 10; s++) {
            int mid = (lo + hi) >> 1;
            if (vs[mid] < th) lo = mid + 1; else hi = mid;
        }
        int t = lo;
        float vmax = vs[1023];
        float etop = src + vmax;
        float mM = (etop >= 0.f) ? etop : 0.2f * etop;
        float E1 = (t < 1024) ? __expf(src - mM) : 0.f;
        float E2 = (t > 0) ? __expf(0.2f * src - mM) : 0.f;
        float rden = 1.f / (E1 * sc1[t] + E2 * sc2[t]);
        qscal_buf[(size_t)bh * N_ + tid] =
            make_float4(E1 * rden, E2 * rden, 0.f, 0.f);

        int cc = t >> 5; if (cc > 31) cc = 31;
        int rr = t - (cc << 5);                    // 0..32
        atomicAdd(&bcnt[cc], 1);
        __syncthreads();
        if (w == 0) {
            int cv = bcnt[lane];
            int inc = cv;
#pragma unroll
            for (int o = 1; o < 32; o <<= 1) {
                int y = __shfl_up_sync(0xffffffffu, inc, o);
                if (lane >= o) inc += y;
            }
            int excl = inc - cv;
            boff[lane] = excl;
            cstart_buf[bh * 33 + lane] = excl;
            if (lane == 31) cstart_buf[bh * 33 + 32] = 1024;
        }
        __syncthreads();
        int pos = atomicAdd(&boff[cc], 1);
        qlist_buf[(size_t)bh * N_ + pos] = (uint32_t)tid | ((uint32_t)rr << 10);
    }

    // vector chunk totals (warp w owns k in [w*32,w*32+32), lane = d), prefetched
    const float* gb = g_buf + (size_t)b * N_ * OCOLS + h * ND;
    float t1 = 0.f, t2v = 0.f;
#pragma unroll
    for (int half = 0; half < 2; half++) {
        float gv[16];
#pragma unroll
        for (int kk = 0; kk < 16; kk++) {
            int k = (w << 5) + half * 16 + kk;
            int j = (int)(su[k] & 1023u);
            gv[kk] = gb[(size_t)j * OCOLS + lane];
        }
#pragma unroll
        for (int kk = 0; kk < 16; kk++) {
            int k = (w << 5) + half * 16 + kk;
            t1 = fmaf(e1s[k], gv[kk], t1);
            t2v = fmaf(e2s[k], gv[kk], t2v);
        }
    }
    tot1[w][lane] = t1;
    tot2[w][lane] = t2v;
    __syncthreads();
    {
        float a1 = tot1[lane][w];   // chunk = lane, d = w
        float a2 = tot2[lane][w];
        float inc1 = a1;
#pragma unroll
        for (int o = 1; o < 32; o <<= 1) {
            float y = __shfl_down_sync(0xffffffffu, inc1, o);
            if (lane + o < 32) inc1 += y;
        }
        float inc2 = a2;
#pragma unroll
        for (int o = 1; o < 32; o <<= 1) {
            float y = __shfl_up_sync(0xffffffffu, inc2, o);
            if (lane >= o) inc2 += y;
        }
        cb1_buf[((size_t)bh * 32 + lane) * 32 + w] = inc1;        // inclusive suffix
        cb2_buf[((size_t)bh * 32 + lane) * 32 + w] = inc2 - a2;   // exclusive prefix
    }
}

// ---------------- kernel 3: fused AV (local prefixes + per-query output) ----------------
// grid (32, 64): one CTA per (chunk, bh). 256 threads = 8 warps.
__global__ __launch_bounds__(256) void av_k(float* __restrict__ out) {
    __shared__ float gsm[32][33];
    __shared__ float P1[33][33];
    __shared__ float P2[33][33];
    __shared__ float b1[32], b2[32], se1[32], se2[32];

    int c = blockIdx.x, bh = blockIdx.y;
    int b = bh >> 3, h = bh & 7;
    int tid = threadIdx.x, w = tid >> 5, lane = tid & 31;
    int k0 = c << 5;

    if (w == 0) {
        b1[lane] = cb1_buf[((size_t)bh * 32 + c) * 32 + lane];
        b2[lane] = cb2_buf[((size_t)bh * 32 + c) * 32 + lane];
    } else if (w == 1) {
        se1[lane] = e1_buf[(size_t)bh * N_ + k0 + lane];
        se2[lane] = e2_buf[(size_t)bh * N_ + k0 + lane];
    }
    // gather 32 g rows: warp w loads rows w, w+8, w+16, w+24 (coalesced 128B each)
    const float* gb = g_buf + (size_t)b * N_ * OCOLS + h * ND;
#pragma unroll
    for (int j = 0; j < 4; j++) {
        int row = w + j * 8;
        int sj = sid_buf[(size_t)bh * N_ + k0 + row];
        gsm[row][lane] = gb[(size_t)sj * OCOLS + lane];
    }
    __syncthreads();

    // warp 0: serial local prefixes (prefetch gsm column into regs first)
    if (w == 0) {
        float gv[32];
#pragma unroll
        for (int r = 0; r < 32; r++) gv[r] = gsm[r][lane];
        float p1 = 0.f, p2 = 0.f;
        P1[0][lane] = 0.f;
        P2[0][lane] = 0.f;
#pragma unroll
        for (int r = 0; r < 32; r++) {
            p1 = fmaf(se1[r], gv[r], p1);
            p2 = fmaf(se2[r], gv[r], p2);
            P1[r + 1][lane] = p1;
            P2[r + 1][lane] = p2;
        }
    }
    __syncthreads();

    int qs = cstart_buf[bh * 33 + c];
    int qe = cstart_buf[bh * 33 + c + 1];
    float base1 = b1[lane], base2 = b2[lane];
    for (int q = qs + w; q < qe; q += 8) {
        uint32_t en = qlist_buf[(size_t)bh * N_ + q];
        int i = (int)(en & 1023u);
        int r = (int)(en >> 10);
        float4 s = qscal_buf[(size_t)bh * N_ + i];
        float o = s.x * (base1 - P1[r][lane]) + s.y * (base2 + P2[r][lane]);
        out[((size_t)(b * N_ + i)) * OCOLS + h * ND + lane] = o;
    }
}

// ---------------- launcher ----------------
extern "C" void kernel_launch(void* const* d_in, const int* in_sizes, int n_in,
                              void* d_out, int out_size) {
    const float* vertex = (const float*)d_in[0];
    const float* w_vert = (const float*)d_in[1];
    const float* attn_w = (const float*)d_in[2];
    float* out = (float*)d_out;

    dim3 gG(2, 128);
    gemm_mma_k<<<gG, 256>>>(vertex, w_vert, attn_w);
    prep_k<<<NBH, 1024>>>();
    av_k<<<dim3(32, NBH), 256>>>(out);
}

// round 8
// speedup vs baseline: 1.8336x; 1.8336x over previous
#include <cuda_runtime.h>
#include <cuda_bf16.h>
#include <cstdint>

// Problem constants
#define B_    8
#define N_    1024
#define FIN   256
#define NH    8
#define ND    32
#define M_TOT (B_ * N_)      // 8192
#define NBH   (B_ * NH)      // 64
#define ROWS  1025
#define OCOLS (NH * ND)      // 256

// ---------------- scratch ----------------
__device__ float g_buf[M_TOT * OCOLS];
__device__ float ssrc_buf[NBH * N_];
__device__ float sdst_buf[NBH * N_];
__device__ int   sid_buf[NBH * N_];
__device__ float e1_buf[NBH * N_];
__device__ float e2_buf[NBH * N_];
__device__ float suf1_buf[NBH * ROWS * ND];
__device__ float pre2_buf[NBH * ROWS * ND];
__device__ float cb1_buf[NBH * 32 * 32];
__device__ float cb2_buf[NBH * 32 * 32];
__device__ float4 qscal_buf[NBH * N_];        // {E1/den, E2/den, bits(t), 0}
__device__ __nv_bfloat16 Wth_buf[OCOLS * FIN];  // W^T hi  [n][k]
__device__ __nv_bfloat16 Wtl_buf[OCOLS * FIN];  // W^T lo  [n][k]

// ---------------- helpers ----------------
#define MMA_BF16(d, a, b)                                                      \
    asm volatile("mma.sync.aligned.m16n8k16.row.col.f32.bf16.bf16.f32 "        \
        "{%0,%1,%2,%3}, {%4,%5,%6,%7}, {%8,%9}, {%0,%1,%2,%3};"                \
        : "+f"((d)[0]), "+f"((d)[1]), "+f"((d)[2]), "+f"((d)[3])               \
        : "r"((a)[0]), "r"((a)[1]), "r"((a)[2]), "r"((a)[3]),                  \
          "r"((b)[0]), "r"((b)[1]))

__device__ __forceinline__ void ldsm4(uint32_t& r0, uint32_t& r1, uint32_t& r2,
                                      uint32_t& r3, uint32_t a) {
    asm volatile("ldmatrix.sync.aligned.m8n8.x4.shared.b16 {%0,%1,%2,%3}, [%4];"
                 : "=r"(r0), "=r"(r1), "=r"(r2), "=r"(r3) : "r"(a));
}

// ---------------- kernel 0: W[k][n] fp32 -> Wt hi/lo [n][k] bf16 ----------------
__global__ __launch_bounds__(256) void trans_k(const float* __restrict__ W) {
    __shared__ float ts[32][33];
    int tk = (blockIdx.x & 7) * 32;      // k tile
    int tn = (blockIdx.x >> 3) * 32;     // n tile
    int r = threadIdx.x >> 5, c = threadIdx.x & 31;
#pragma unroll
    for (int j = 0; j < 4; j++)
        ts[r + j * 8][c] = W[(size_t)(tk + r + j * 8) * OCOLS + tn + c];
    __syncthreads();
#pragma unroll
    for (int j = 0; j < 4; j++) {
        int n = r + j * 8;
        float x = ts[c][n];
        __nv_bfloat16 h = __float2bfloat16(x);
        Wth_buf[(size_t)(tn + n) * FIN + tk + c] = h;
        Wtl_buf[(size_t)(tn + n) * FIN + tk + c] =
            __float2bfloat16(x - __bfloat162float(h));
    }
}

// ---------------- kernel 1: GEMM via HMMA + LDSM, fused score epilogue ----------------
#define SA 40   // smem row stride in bf16 (80 B, 16B-multiple, conflict-free ldmatrix)
__global__ __launch_bounds__(256) void gemm_mma_k(const float* __restrict__ A,
                                                  const float* __restrict__ attn_w) {
    __shared__ __align__(16) __nv_bfloat16 Ah[64 * SA];
    __shared__ __align__(16) __nv_bfloat16 Al[64 * SA];
    __shared__ __align__(16) __nv_bfloat16 Bh[128 * SA];
    __shared__ __align__(16) __nv_bfloat16 Bl[128 * SA];

    const int tid = threadIdx.x;
    const int wid = tid >> 5, lane = tid & 31;
    const int wm = wid >> 2, wn = wid & 3;
    const int rowBase = blockIdx.y * 64;
    const int colBase = blockIdx.x * 128;
    const int g = lane >> 2, tg = lane & 3;

    // staging coords
    const int ar0 = tid >> 3, ac4 = (tid & 7) << 2;   // A: 2 its, rows ar0, ar0+32
    const int br = tid >> 2, bc = tid & 3;            // B: 2 its, rows br, br+64 (16B chunk bc)

    const uint32_t sAh = (uint32_t)__cvta_generic_to_shared(Ah);
    const uint32_t sAl = (uint32_t)__cvta_generic_to_shared(Al);
    const uint32_t sBh = (uint32_t)__cvta_generic_to_shared(Bh);
    const uint32_t sBl = (uint32_t)__cvta_generic_to_shared(Bl);

    // lane-dependent ldmatrix base offsets (bytes)
    const uint32_t aoff = (uint32_t)(((lane & 15) * SA + ((lane >> 4) << 3)) * 2);
    const uint32_t boff = (uint32_t)((((lane & 7) + ((lane >> 4) << 3)) * SA
                                      + (((lane >> 3) & 1) << 3)) * 2);

    float acc[2][4][4];
#pragma unroll
    for (int mt = 0; mt < 2; mt++)
#pragma unroll
        for (int nt = 0; nt < 4; nt++)
#pragma unroll
            for (int r = 0; r < 4; r++) acc[mt][nt][r] = 0.f;

    const uint4* Wth4 = (const uint4*)Wth_buf;  // row stride 32 uint4
    const uint4* Wtl4 = (const uint4*)Wtl_buf;

    float4 pa[2]; uint4 pbh[2], pbl[2];
    pa[0] = *(const float4*)(A + (size_t)(rowBase + ar0) * FIN + ac4);
    pa[1] = *(const float4*)(A + (size_t)(rowBase + ar0 + 32) * FIN + ac4);
#pragma unroll
    for (int it = 0; it < 2; it++) {
        int row = br + it * 64;
        pbh[it] = Wth4[(size_t)(colBase + row) * 32 + bc];
        pbl[it] = Wtl4[(size_t)(colBase + row) * 32 + bc];
    }

    for (int kc = 0; kc < 8; kc++) {
        __syncthreads();
        // stage A (split hi/lo)
#pragma unroll
        for (int it = 0; it < 2; it++) {
            int r = ar0 + it * 32;
            float xs[4] = {pa[it].x, pa[it].y, pa[it].z, pa[it].w};
#pragma unroll
            for (int c = 0; c < 4; c++) {
                __nv_bfloat16 h = __float2bfloat16(xs[c]);
                Ah[r * SA + ac4 + c] = h;
                Al[r * SA + ac4 + c] = __float2bfloat16(xs[c] - __bfloat162float(h));
            }
        }
        // stage B (already bf16, 16B row stores, conflict-free)
#pragma unroll
        for (int it = 0; it < 2; it++) {
            int row = br + it * 64;
            *(uint4*)&Bh[row * SA + bc * 8] = pbh[it];
            *(uint4*)&Bl[row * SA + bc * 8] = pbl[it];
        }
        __syncthreads();

        if (kc < 7) {
            int k0 = (kc + 1) * 32;
            pa[0] = *(const float4*)(A + (size_t)(rowBase + ar0) * FIN + k0 + ac4);
            pa[1] = *(const float4*)(A + (size_t)(rowBase + ar0 + 32) * FIN + k0 + ac4);
#pragma unroll
            for (int it = 0; it < 2; it++) {
                int row = br + it * 64;
                pbh[it] = Wth4[(size_t)(colBase + row) * 32 + (kc + 1) * 4 + bc];
                pbl[it] = Wtl4[(size_t)(colBase + row) * 32 + (kc + 1) * 4 + bc];
            }
        }

#pragma unroll
        for (int ks = 0; ks < 2; ks++) {
            const uint32_t kb = (uint32_t)(ks * 16 * 2);
            uint32_t ah[2][4], al[2][4], bb[4][2];
#pragma unroll
            for (int mt = 0; mt < 2; mt++) {
                uint32_t ro = (uint32_t)((wm * 32 + mt * 16) * SA * 2);
                ldsm4(ah[mt][0], ah[mt][1], ah[mt][2], ah[mt][3], sAh + aoff + ro + kb);
                ldsm4(al[mt][0], al[mt][1], al[mt][2], al[mt][3], sAl + aoff + ro + kb);
            }
#pragma unroll
            for (int p = 0; p < 2; p++) {
                uint32_t ro = (uint32_t)((wn * 32 + p * 16) * SA * 2);
                ldsm4(bb[2 * p][0], bb[2 * p][1], bb[2 * p + 1][0], bb[2 * p + 1][1],
                      sBh + boff + ro + kb);
            }
#pragma unroll
            for (int mt = 0; mt < 2; mt++)
#pragma unroll
                for (int nt = 0; nt < 4; nt++) {
                    MMA_BF16(acc[mt][nt], ah[mt], bb[nt]);   // hi*hi
                    MMA_BF16(acc[mt][nt], al[mt], bb[nt]);   // lo*hi
                }
#pragma unroll
            for (int p = 0; p < 2; p++) {
                uint32_t ro = (uint32_t)((wn * 32 + p * 16) * SA * 2);
                ldsm4(bb[2 * p][0], bb[2 * p][1], bb[2 * p + 1][0], bb[2 * p + 1][1],
                      sBl + boff + ro + kb);
            }
#pragma unroll
            for (int mt = 0; mt < 2; mt++)
#pragma unroll
                for (int nt = 0; nt < 4; nt++)
                    MMA_BF16(acc[mt][nt], ah[mt], bb[nt]);   // hi*lo
        }
    }

    // epilogue: write g
#pragma unroll
    for (int mt = 0; mt < 2; mt++) {
        int r0 = rowBase + wm * 32 + mt * 16 + g;
#pragma unroll
        for (int nt = 0; nt < 4; nt++) {
            int c0 = colBase + wn * 32 + nt * 8 + tg * 2;
            *(float2*)(g_buf + (size_t)r0 * OCOLS + c0) =
                make_float2(acc[mt][nt][0], acc[mt][nt][1]);
            *(float2*)(g_buf + (size_t)(r0 + 8) * OCOLS + c0) =
                make_float2(acc[mt][nt][2], acc[mt][nt][3]);
        }
    }

    // fused score
    {
        float ws[4][2], wd[4][2];
#pragma unroll
        for (int nt = 0; nt < 4; nt++)
#pragma unroll
            for (int j = 0; j < 2; j++) {
                int d = nt * 8 + tg * 2 + j;
                ws[nt][j] = attn_w[d];
                wd[nt][j] = attn_w[32 + d];
            }
        int hh = blockIdx.x * 4 + wn;
#pragma unroll
        for (int mt = 0; mt < 2; mt++)
#pragma unroll
            for (int rh = 0; rh < 2; rh++) {
                float as = 0.f, ad = 0.f;
#pragma unroll
                for (int nt = 0; nt < 4; nt++) {
                    as += acc[mt][nt][rh * 2] * ws[nt][0] + acc[mt][nt][rh * 2 + 1] * ws[nt][1];
                    ad += acc[mt][nt][rh * 2] * wd[nt][0] + acc[mt][nt][rh * 2 + 1] * wd[nt][1];
                }
                as += __shfl_xor_sync(0xffffffffu, as, 1);
                as += __shfl_xor_sync(0xffffffffu, as, 2);
                ad += __shfl_xor_sync(0xffffffffu, ad, 1);
                ad += __shfl_xor_sync(0xffffffffu, ad, 2);
                if (tg == 0) {
                    int m = rowBase + wm * 32 + mt * 16 + rh * 8 + g;
                    int b = m >> 10, i = m & 1023;
                    ssrc_buf[(size_t)(b * NH + hh) * N_ + i] = as;
                    sdst_buf[(size_t)(b * NH + hh) * N_ + i] = ad;
                }
            }
    }
}

// ---------------- kernel 2: sort + scans + chunk bases + fused query scalars ----------------
__device__ __forceinline__ void warp_passes_u(uint32_t& key, int k, int jmax, int tid) {
    for (int j = jmax; j > 0; j >>= 1) {
        uint32_t pk = __shfl_xor_sync(0xffffffffu, key, j);
        bool lower = ((tid & j) == 0);
        bool up = ((tid & k) == 0);
        bool keepmin = (lower == up);
        bool sw = keepmin ? (key > pk) : (key < pk);
        if (sw) key = pk;
    }
}

__global__ __launch_bounds__(1024) void prep_k() {
    __shared__ uint32_t su[1024];
    __shared__ float vs[1024];
    __shared__ float e1s[1024];
    __shared__ float e2s[1024];
    __shared__ float sc1[ROWS];
    __shared__ float sc2[ROWS];
    __shared__ float wt[32], wo[32], wt2[32], wo2[32];
    __shared__ float tot1[32][33];
    __shared__ float tot2[32][33];

    int bh = blockIdx.x;
    int b = bh >> 3, h = bh & 7;
    int tid = threadIdx.x;
    int w = tid >> 5, lane = tid & 31;

    float v0 = sdst_buf[(size_t)bh * N_ + tid];
    uint32_t u = __float_as_uint(v0);
    u = (u & 0x80000000u) ? ~u : (u | 0x80000000u);
    uint32_t key = (u & 0xFFFFFC00u) | (uint32_t)tid;

#pragma unroll
    for (int k = 2; k <= 32; k <<= 1) warp_passes_u(key, k, k >> 1, tid);
    su[tid] = key;
    __syncthreads();
    for (int k = 64; k <= 1024; k <<= 1) {
        for (int j = k >> 1; j >= 32; j >>= 1) {
            int ixj = tid ^ j;
            if (ixj > tid) {
                bool up = ((tid & k) == 0);
                uint32_t a = su[tid], c = su[ixj];
                bool sw = up ? (a > c) : (a < c);
                if (sw) { su[tid] = c; su[ixj] = a; }
            }
            __syncthreads();
        }
        key = su[tid];
        warp_passes_u(key, k, 16, tid);
        su[tid] = key;
        __syncthreads();
    }

    int idj = (int)(key & 1023u);
    float rv = sdst_buf[(size_t)bh * N_ + idj];
    vs[tid] = rv;
    sid_buf[(size_t)bh * N_ + tid] = idj;
    float x1 = __expf(rv);
    float x2 = __expf(0.2f * rv);
    e1s[tid] = x1; e2s[tid] = x2;
    e1_buf[(size_t)bh * N_ + tid] = x1;
    e2_buf[(size_t)bh * N_ + tid] = x2;

    float s2 = x2;
#pragma unroll
    for (int o = 1; o < 32; o <<= 1) {
        float y = __shfl_up_sync(0xffffffffu, s2, o);
        if (lane >= o) s2 += y;
    }
    if (lane == 31) wt2[w] = s2;
    float s1 = x1;
#pragma unroll
    for (int o = 1; o < 32; o <<= 1) {
        float y = __shfl_down_sync(0xffffffffu, s1, o);
        if (lane + o < 32) s1 += y;
    }
    if (lane == 0) wt[w] = s1;
    __syncthreads();
    if (w == 0) {
        float t = wt[lane];
        float ts = t;
#pragma unroll
        for (int o = 1; o < 32; o <<= 1) {
            float y = __shfl_down_sync(0xffffffffu, ts, o);
            if (lane + o < 32) ts += y;
        }
        wo[lane] = ts - t;
        float t2 = wt2[lane];
        float ps = t2;
#pragma unroll
        for (int o = 1; o < 32; o <<= 1) {
            float y = __shfl_up_sync(0xffffffffu, ps, o);
            if (lane >= o) ps += y;
        }
        wo2[lane] = ps - t2;
    }
    __syncthreads();
    sc1[tid] = s1 + wo[w];
    sc2[tid + 1] = s2 + wo2[w];
    if (tid == 0) {
        sc1[1024] = 0.f;
        sc2[0] = 0.f;
    }
    __syncthreads();

    // fused per-query scalars
    {
        float src = ssrc_buf[(size_t)bh * N_ + tid];
        float th = -src;
        int lo = 0, hi = 1024;
#pragma unroll
        for (int s = 0; s < 10; s++) {
            int mid = (lo + hi) >> 1;
            if (vs[mid] < th) lo = mid + 1; else hi = mid;
        }
        int t = lo;
        float vmax = vs[1023];
        float etop = src + vmax;
        float mM = (etop >= 0.f) ? etop : 0.2f * etop;
        float E1 = (t < 1024) ? __expf(src - mM) : 0.f;
        float E2 = (t > 0) ? __expf(0.2f * src - mM) : 0.f;
        float rden = 1.f / (E1 * sc1[t] + E2 * sc2[t]);
        qscal_buf[(size_t)bh * N_ + tid] =
            make_float4(E1 * rden, E2 * rden, __int_as_float(t), 0.f);
    }

    // vector chunk totals (prefetched)
    const float* gb = g_buf + (size_t)b * N_ * OCOLS + h * ND;
    float t1 = 0.f, t2v = 0.f;
#pragma unroll
    for (int half = 0; half < 2; half++) {
        float gv[16];
#pragma unroll
        for (int kk = 0; kk < 16; kk++) {
            int k = (w << 5) + half * 16 + kk;
            int j = (int)(su[k] & 1023u);
            gv[kk] = gb[(size_t)j * OCOLS + lane];
        }
#pragma unroll
        for (int kk = 0; kk < 16; kk++) {
            int k = (w << 5) + half * 16 + kk;
            t1 = fmaf(e1s[k], gv[kk], t1);
            t2v = fmaf(e2s[k], gv[kk], t2v);
        }
    }
    tot1[w][lane] = t1;
    tot2[w][lane] = t2v;
    __syncthreads();
    {
        float a1 = tot1[lane][w];
        float a2 = tot2[lane][w];
        float inc1 = a1;
#pragma unroll
        for (int o = 1; o < 32; o <<= 1) {
            float y = __shfl_down_sync(0xffffffffu, inc1, o);
            if (lane + o < 32) inc1 += y;
        }
        float inc2 = a2;
#pragma unroll
        for (int o = 1; o < 32; o <<= 1) {
            float y = __shfl_up_sync(0xffffffffu, inc2, o);
            if (lane >= o) inc2 += y;
        }
        cb1_buf[((size_t)bh * 32 + lane) * 32 + w] = inc1;
        cb2_buf[((size_t)bh * 32 + lane) * 32 + w] = inc2 - a2;
    }
}

// ---------------- kernel 3: merged prefix/suffix writes ----------------
__global__ __launch_bounds__(256, 2) void write_k() {
    int bh = blockIdx.y;
    int b = bh >> 3, h = bh & 7;
    int wi = threadIdx.x >> 5, lane = threadIdx.x & 31;
    int c = blockIdx.x * 8 + wi;
    int k0 = c << 5;

    float is1 = cb1_buf[((size_t)bh * 32 + c) * 32 + lane];
    float r2  = cb2_buf[((size_t)bh * 32 + c) * 32 + lane];
    const float* gb = g_buf + (size_t)b * N_ * OCOLS + h * ND;
    const int* sidp = sid_buf + (size_t)bh * N_ + k0;
    const float* e1p = e1_buf + (size_t)bh * N_ + k0;
    const float* e2p = e2_buf + (size_t)bh * N_ + k0;
    float* S1 = suf1_buf + (size_t)bh * ROWS * ND;
    float* P2 = pre2_buf + (size_t)bh * ROWS * ND;

    if (c == 0) P2[lane] = 0.f;

    float gv[32];
#pragma unroll
    for (int kk = 0; kk < 32; kk++)
        gv[kk] = gb[(size_t)sidp[kk] * OCOLS + lane];

    float p1 = 0.f;
#pragma unroll
    for (int kk = 0; kk < 32; kk++) {
        int k = k0 + kk;
        S1[(size_t)k * ND + lane] = is1 - p1;
        p1 = fmaf(e1p[kk], gv[kk], p1);
        r2 = fmaf(e2p[kk], gv[kk], r2);
        P2[(size_t)(k + 1) * ND + lane] = r2;
    }
    if (c == 31) S1[(size_t)1024 * ND + lane] = 0.f;
}

// ---------------- kernel 4: output ----------------
__global__ __launch_bounds__(256) void out_k(float* __restrict__ out) {
    int idx = blockIdx.x * 256 + threadIdx.x;
    int e = idx << 2;
    int m = e >> 8, cc = e & 255;
    int h = cc >> 5, d0 = cc & 31;
    int b = m >> 10, i = m & 1023;
    int bh = b * NH + h;
    float4 s = qscal_buf[(size_t)bh * N_ + i];
    int t = __float_as_int(s.z);
    size_t base = ((size_t)bh * ROWS + t) * ND + d0;
    float4 sf = *(const float4*)(suf1_buf + base);
    float4 pf = *(const float4*)(pre2_buf + base);
    float4 o;
    o.x = s.x * sf.x + s.y * pf.x;
    o.y = s.x * sf.y + s.y * pf.y;
    o.z = s.x * sf.z + s.y * pf.z;
    o.w = s.x * sf.w + s.y * pf.w;
    *(float4*)(out + e) = o;
}

// ---------------- launcher ----------------
extern "C" void kernel_launch(void* const* d_in, const int* in_sizes, int n_in,
                              void* d_out, int out_size) {
    const float* vertex = (const float*)d_in[0];
    const float* w_vert = (const float*)d_in[1];
    const float* attn_w = (const float*)d_in[2];
    float* out = (float*)d_out;

    trans_k<<<64, 256>>>(w_vert);
    dim3 gG(2, 128);
    gemm_mma_k<<<gG, 256>>>(vertex, attn_w);
    prep_k<<<NBH, 1024>>>();
    write_k<<<dim3(4, NBH), 256>>>();
    out_k<<<M_TOT * OCOLS / 4 / 256, 256>>>(out);
}

// round 9
// speedup vs baseline: 1.8364x; 1.0015x over previous
#include <cuda_runtime.h>
#include <cuda_bf16.h>
#include <cstdint>

// Problem constants
#define B_    8
#define N_    1024
#define FIN   256
#define NH    8
#define ND    32
#define M_TOT (B_ * N_)      // 8192
#define NBH   (B_ * NH)      // 64
#define ROWS  1025
#define OCOLS (NH * ND)      // 256

// ---------------- scratch ----------------
__device__ float g_buf[M_TOT * OCOLS];
__device__ float ssrc_buf[NBH * N_];
__device__ float sdst_buf[NBH * N_];
__device__ int   sid_buf[NBH * N_];
__device__ float e1_buf[NBH * N_];
__device__ float e2_buf[NBH * N_];
__device__ float suf1_buf[NBH * ROWS * ND];
__device__ float pre2_buf[NBH * ROWS * ND];
__device__ float cb1_buf[NBH * 32 * 32];
__device__ float cb2_buf[NBH * 32 * 32];
__device__ float4 qscal_buf[NBH * N_];        // {E1/den, E2/den, bits(t), 0}
__device__ __nv_bfloat16 Wth_buf[OCOLS * FIN];  // W^T hi  [n][k]
__device__ __nv_bfloat16 Wtl_buf[OCOLS * FIN];  // W^T lo  [n][k]

// ---------------- helpers ----------------
#define MMA_BF16(d, a, b)                                                      \
    asm volatile("mma.sync.aligned.m16n8k16.row.col.f32.bf16.bf16.f32 "        \
        "{%0,%1,%2,%3}, {%4,%5,%6,%7}, {%8,%9}, {%0,%1,%2,%3};"                \
        : "+f"((d)[0]), "+f"((d)[1]), "+f"((d)[2]), "+f"((d)[3])               \
        : "r"((a)[0]), "r"((a)[1]), "r"((a)[2]), "r"((a)[3]),                  \
          "r"((b)[0]), "r"((b)[1]))

__device__ __forceinline__ void ldsm4(uint32_t& r0, uint32_t& r1, uint32_t& r2,
                                      uint32_t& r3, uint32_t a) {
    asm volatile("ldmatrix.sync.aligned.m8n8.x4.shared.b16 {%0,%1,%2,%3}, [%4];"
                 : "=r"(r0), "=r"(r1), "=r"(r2), "=r"(r3) : "r"(a));
}

// ---------------- kernel 0: W[k][n] fp32 -> Wt hi/lo [n][k] bf16 ----------------
__global__ __launch_bounds__(256) void trans_k(const float* __restrict__ W) {
    __shared__ float ts[32][33];
    int tk = (blockIdx.x & 7) * 32;      // k tile
    int tn = (blockIdx.x >> 3) * 32;     // n tile
    int r = threadIdx.x >> 5, c = threadIdx.x & 31;
#pragma unroll
    for (int j = 0; j < 4; j++)
        ts[r + j * 8][c] = W[(size_t)(tk + r + j * 8) * OCOLS + tn + c];
    __syncthreads();
#pragma unroll
    for (int j = 0; j < 4; j++) {
        int n = r + j * 8;
        float x = ts[c][n];
        __nv_bfloat16 h = __float2bfloat16(x);
        Wth_buf[(size_t)(tn + n) * FIN + tk + c] = h;
        Wtl_buf[(size_t)(tn + n) * FIN + tk + c] =
            __float2bfloat16(x - __bfloat162float(h));
    }
}

// ---------------- kernel 1: GEMM via HMMA + LDSM, fused score epilogue ----------------
#define SA 40   // smem row stride in bf16 (80 B, 16B-multiple, conflict-free ldmatrix)
__global__ __launch_bounds__(256) void gemm_mma_k(const float* __restrict__ A,
                                                  const float* __restrict__ attn_w) {
    __shared__ __align__(16) __nv_bfloat16 Ah[64 * SA];
    __shared__ __align__(16) __nv_bfloat16 Al[64 * SA];
    __shared__ __align__(16) __nv_bfloat16 Bh[128 * SA];
    __shared__ __align__(16) __nv_bfloat16 Bl[128 * SA];

    const int tid = threadIdx.x;
    const int wid = tid >> 5, lane = tid & 31;
    const int wm = wid >> 2, wn = wid & 3;
    const int rowBase = blockIdx.y * 64;
    const int colBase = blockIdx.x * 128;
    const int g = lane >> 2, tg = lane & 3;

    const int ar0 = tid >> 3, ac4 = (tid & 7) << 2;
    const int br = tid >> 2, bc = tid & 3;

    const uint32_t sAh = (uint32_t)__cvta_generic_to_shared(Ah);
    const uint32_t sAl = (uint32_t)__cvta_generic_to_shared(Al);
    const uint32_t sBh = (uint32_t)__cvta_generic_to_shared(Bh);
    const uint32_t sBl = (uint32_t)__cvta_generic_to_shared(Bl);

    const uint32_t aoff = (uint32_t)(((lane & 15) * SA + ((lane >> 4) << 3)) * 2);
    const uint32_t boff = (uint32_t)((((lane & 7) + ((lane >> 4) << 3)) * SA
                                      + (((lane >> 3) & 1) << 3)) * 2);

    float acc[2][4][4];
#pragma unroll
    for (int mt = 0; mt < 2; mt++)
#pragma unroll
        for (int nt = 0; nt < 4; nt++)
#pragma unroll
            for (int r = 0; r < 4; r++) acc[mt][nt][r] = 0.f;

    const uint4* Wth4 = (const uint4*)Wth_buf;
    const uint4* Wtl4 = (const uint4*)Wtl_buf;

    float4 pa[2]; uint4 pbh[2], pbl[2];
    pa[0] = *(const float4*)(A + (size_t)(rowBase + ar0) * FIN + ac4);
    pa[1] = *(const float4*)(A + (size_t)(rowBase + ar0 + 32) * FIN + ac4);
#pragma unroll
    for (int it = 0; it < 2; it++) {
        int row = br + it * 64;
        pbh[it] = Wth4[(size_t)(colBase + row) * 32 + bc];
        pbl[it] = Wtl4[(size_t)(colBase + row) * 32 + bc];
    }

    for (int kc = 0; kc < 8; kc++) {
        __syncthreads();
#pragma unroll
        for (int it = 0; it < 2; it++) {
            int r = ar0 + it * 32;
            float xs[4] = {pa[it].x, pa[it].y, pa[it].z, pa[it].w};
#pragma unroll
            for (int c = 0; c < 4; c++) {
                __nv_bfloat16 h = __float2bfloat16(xs[c]);
                Ah[r * SA + ac4 + c] = h;
                Al[r * SA + ac4 + c] = __float2bfloat16(xs[c] - __bfloat162float(h));
            }
        }
#pragma unroll
        for (int it = 0; it < 2; it++) {
            int row = br + it * 64;
            *(uint4*)&Bh[row * SA + bc * 8] = pbh[it];
            *(uint4*)&Bl[row * SA + bc * 8] = pbl[it];
        }
        __syncthreads();

        if (kc < 7) {
            int k0 = (kc + 1) * 32;
            pa[0] = *(const float4*)(A + (size_t)(rowBase + ar0) * FIN + k0 + ac4);
            pa[1] = *(const float4*)(A + (size_t)(rowBase + ar0 + 32) * FIN + k0 + ac4);
#pragma unroll
            for (int it = 0; it < 2; it++) {
                int row = br + it * 64;
                pbh[it] = Wth4[(size_t)(colBase + row) * 32 + (kc + 1) * 4 + bc];
                pbl[it] = Wtl4[(size_t)(colBase + row) * 32 + (kc + 1) * 4 + bc];
            }
        }

#pragma unroll
        for (int ks = 0; ks < 2; ks++) {
            const uint32_t kb = (uint32_t)(ks * 16 * 2);
            uint32_t ah[2][4], al[2][4], bb[4][2];
#pragma unroll
            for (int mt = 0; mt < 2; mt++) {
                uint32_t ro = (uint32_t)((wm * 32 + mt * 16) * SA * 2);
                ldsm4(ah[mt][0], ah[mt][1], ah[mt][2], ah[mt][3], sAh + aoff + ro + kb);
                ldsm4(al[mt][0], al[mt][1], al[mt][2], al[mt][3], sAl + aoff + ro + kb);
            }
#pragma unroll
            for (int p = 0; p < 2; p++) {
                uint32_t ro = (uint32_t)((wn * 32 + p * 16) * SA * 2);
                ldsm4(bb[2 * p][0], bb[2 * p][1], bb[2 * p + 1][0], bb[2 * p + 1][1],
                      sBh + boff + ro + kb);
            }
#pragma unroll
            for (int mt = 0; mt < 2; mt++)
#pragma unroll
                for (int nt = 0; nt < 4; nt++) {
                    MMA_BF16(acc[mt][nt], ah[mt], bb[nt]);
                    MMA_BF16(acc[mt][nt], al[mt], bb[nt]);
                }
#pragma unroll
            for (int p = 0; p < 2; p++) {
                uint32_t ro = (uint32_t)((wn * 32 + p * 16) * SA * 2);
                ldsm4(bb[2 * p][0], bb[2 * p][1], bb[2 * p + 1][0], bb[2 * p + 1][1],
                      sBl + boff + ro + kb);
            }
#pragma unroll
            for (int mt = 0; mt < 2; mt++)
#pragma unroll
                for (int nt = 0; nt < 4; nt++)
                    MMA_BF16(acc[mt][nt], ah[mt], bb[nt]);
        }
    }

#pragma unroll
    for (int mt = 0; mt < 2; mt++) {
        int r0 = rowBase + wm * 32 + mt * 16 + g;
#pragma unroll
        for (int nt = 0; nt < 4; nt++) {
            int c0 = colBase + wn * 32 + nt * 8 + tg * 2;
            *(float2*)(g_buf + (size_t)r0 * OCOLS + c0) =
                make_float2(acc[mt][nt][0], acc[mt][nt][1]);
            *(float2*)(g_buf + (size_t)(r0 + 8) * OCOLS + c0) =
                make_float2(acc[mt][nt][2], acc[mt][nt][3]);
        }
    }

    // fused score
    {
        float ws[4][2], wd[4][2];
#pragma unroll
        for (int nt = 0; nt < 4; nt++)
#pragma unroll
            for (int j = 0; j < 2; j++) {
                int d = nt * 8 + tg * 2 + j;
                ws[nt][j] = attn_w[d];
                wd[nt][j] = attn_w[32 + d];
            }
        int hh = blockIdx.x * 4 + wn;
#pragma unroll
        for (int mt = 0; mt < 2; mt++)
#pragma unroll
            for (int rh = 0; rh < 2; rh++) {
                float as = 0.f, ad = 0.f;
#pragma unroll
                for (int nt = 0; nt < 4; nt++) {
                    as += acc[mt][nt][rh * 2] * ws[nt][0] + acc[mt][nt][rh * 2 + 1] * ws[nt][1];
                    ad += acc[mt][nt][rh * 2] * wd[nt][0] + acc[mt][nt][rh * 2 + 1] * wd[nt][1];
                }
                as += __shfl_xor_sync(0xffffffffu, as, 1);
                as += __shfl_xor_sync(0xffffffffu, as, 2);
                ad += __shfl_xor_sync(0xffffffffu, ad, 1);
                ad += __shfl_xor_sync(0xffffffffu, ad, 2);
                if (tg == 0) {
                    int m = rowBase + wm * 32 + mt * 16 + rh * 8 + g;
                    int b = m >> 10, i = m & 1023;
                    ssrc_buf[(size_t)(b * NH + hh) * N_ + i] = as;
                    sdst_buf[(size_t)(b * NH + hh) * N_ + i] = ad;
                }
            }
    }
}

// ---------------- kernel 2: sort + scans + chunk bases + fused query scalars ----------------
__device__ __forceinline__ void warp_passes_u(uint32_t& key, int k, int jmax, int tid) {
    for (int j = jmax; j > 0; j >>= 1) {
        uint32_t pk = __shfl_xor_sync(0xffffffffu, key, j);
        bool lower = ((tid & j) == 0);
        bool up = ((tid & k) == 0);
        bool keepmin = (lower == up);
        bool sw = keepmin ? (key > pk) : (key < pk);
        if (sw) key = pk;
    }
}

__global__ __launch_bounds__(1024) void prep_k() {
    __shared__ uint32_t su[1024];
    __shared__ float vs[1024];
    __shared__ float e1s[1024];
    __shared__ float e2s[1024];
    __shared__ float sc1[ROWS];
    __shared__ float sc2[ROWS];
    __shared__ float wt[32], wo[32], wt2[32], wo2[32];
    __shared__ float tot1[32][33];
    __shared__ float tot2[32][33];

    int bh = blockIdx.x;
    int b = bh >> 3, h = bh & 7;
    int tid = threadIdx.x;
    int w = tid >> 5, lane = tid & 31;

    float v0 = sdst_buf[(size_t)bh * N_ + tid];
    uint32_t u = __float_as_uint(v0);
    u = (u & 0x80000000u) ? ~u : (u | 0x80000000u);
    uint32_t key = (u & 0xFFFFFC00u) | (uint32_t)tid;

#pragma unroll
    for (int k = 2; k <= 32; k <<= 1) warp_passes_u(key, k, k >> 1, tid);
    su[tid] = key;
    __syncthreads();
    for (int k = 64; k <= 1024; k <<= 1) {
        for (int j = k >> 1; j >= 32; j >>= 1) {
            int ixj = tid ^ j;
            if (ixj > tid) {
                bool up = ((tid & k) == 0);
                uint32_t a = su[tid], c = su[ixj];
                bool sw = up ? (a > c) : (a < c);
                if (sw) { su[tid] = c; su[ixj] = a; }
            }
            __syncthreads();
        }
        key = su[tid];
        warp_passes_u(key, k, 16, tid);
        su[tid] = key;
        __syncthreads();
    }

    int idj = (int)(key & 1023u);
    float rv = sdst_buf[(size_t)bh * N_ + idj];
    vs[tid] = rv;
    sid_buf[(size_t)bh * N_ + tid] = idj;
    float x1 = __expf(rv);
    float x2 = __expf(0.2f * rv);
    e1s[tid] = x1; e2s[tid] = x2;
    e1_buf[(size_t)bh * N_ + tid] = x1;
    e2_buf[(size_t)bh * N_ + tid] = x2;

    float s2 = x2;
#pragma unroll
    for (int o = 1; o < 32; o <<= 1) {
        float y = __shfl_up_sync(0xffffffffu, s2, o);
        if (lane >= o) s2 += y;
    }
    if (lane == 31) wt2[w] = s2;
    float s1 = x1;
#pragma unroll
    for (int o = 1; o < 32; o <<= 1) {
        float y = __shfl_down_sync(0xffffffffu, s1, o);
        if (lane + o < 32) s1 += y;
    }
    if (lane == 0) wt[w] = s1;
    __syncthreads();
    if (w == 0) {
        float t = wt[lane];
        float ts = t;
#pragma unroll
        for (int o = 1; o < 32; o <<= 1) {
            float y = __shfl_down_sync(0xffffffffu, ts, o);
            if (lane + o < 32) ts += y;
        }
        wo[lane] = ts - t;
        float t2 = wt2[lane];
        float ps = t2;
#pragma unroll
        for (int o = 1; o < 32; o <<= 1) {
            float y = __shfl_up_sync(0xffffffffu, ps, o);
            if (lane >= o) ps += y;
        }
        wo2[lane] = ps - t2;
    }
    __syncthreads();
    sc1[tid] = s1 + wo[w];
    sc2[tid + 1] = s2 + wo2[w];
    if (tid == 0) {
        sc1[1024] = 0.f;
        sc2[0] = 0.f;
    }
    __syncthreads();

    // fused per-query scalars
    {
        float src = ssrc_buf[(size_t)bh * N_ + tid];
        float th = -src;
        int lo = 0, hi = 1024;
#pragma unroll
        for (int s = 0; s < 10; s++) {
            int mid = (lo + hi) >> 1;
            if (vs[mid] < th) lo = mid + 1; else hi = mid;
        }
        int t = lo;
        float vmax = vs[1023];
        float etop = src + vmax;
        float mM = (etop >= 0.f) ? etop : 0.2f * etop;
        float E1 = (t < 1024) ? __expf(src - mM) : 0.f;
        float E2 = (t > 0) ? __expf(0.2f * src - mM) : 0.f;
        float rden = 1.f / (E1 * sc1[t] + E2 * sc2[t]);
        qscal_buf[(size_t)bh * N_ + tid] =
            make_float4(E1 * rden, E2 * rden, __int_as_float(t), 0.f);
    }

    // vector chunk totals (prefetched)
    const float* gb = g_buf + (size_t)b * N_ * OCOLS + h * ND;
    float t1 = 0.f, t2v = 0.f;
#pragma unroll
    for (int half = 0; half < 2; half++) {
        float gv[16];
#pragma unroll
        for (int kk = 0; kk < 16; kk++) {
            int k = (w << 5) + half * 16 + kk;
            int j = (int)(su[k] & 1023u);
            gv[kk] = gb[(size_t)j * OCOLS + lane];
        }
#pragma unroll
        for (int kk = 0; kk < 16; kk++) {
            int k = (w << 5) + half * 16 + kk;
            t1 = fmaf(e1s[k], gv[kk], t1);
            t2v = fmaf(e2s[k], gv[kk], t2v);
        }
    }
    tot1[w][lane] = t1;
    tot2[w][lane] = t2v;
    __syncthreads();
    {
        float a1 = tot1[lane][w];
        float a2 = tot2[lane][w];
        float inc1 = a1;
#pragma unroll
        for (int o = 1; o < 32; o <<= 1) {
            float y = __shfl_down_sync(0xffffffffu, inc1, o);
            if (lane + o < 32) inc1 += y;
        }
        float inc2 = a2;
#pragma unroll
        for (int o = 1; o < 32; o <<= 1) {
            float y = __shfl_up_sync(0xffffffffu, inc2, o);
            if (lane >= o) inc2 += y;
        }
        cb1_buf[((size_t)bh * 32 + lane) * 32 + w] = inc1;
        cb2_buf[((size_t)bh * 32 + lane) * 32 + w] = inc2 - a2;
    }
}

// ---------------- kernel 3: merged prefix/suffix writes (warp-pair split) ----------------
// grid (8, 64), 256 threads = 8 warps = 4 chunk-pairs. Chunk c = bx*4 + (w>>1).
__global__ __launch_bounds__(256) void write_k() {
    __shared__ float hs1[4][32];   // half-0 sums per chunk-pair
    __shared__ float hs2[4][32];

    int bh = blockIdx.y;
    int b = bh >> 3, h = bh & 7;
    int w = threadIdx.x >> 5, lane = threadIdx.x & 31;
    int j = w >> 1, half = w & 1;
    int c = blockIdx.x * 4 + j;
    int k0 = (c << 5) + half * 16;

    const float* gb = g_buf + (size_t)b * N_ * OCOLS + h * ND;
    const int* sidp = sid_buf + (size_t)bh * N_ + k0;
    const float* e1p = e1_buf + (size_t)bh * N_ + k0;
    const float* e2p = e2_buf + (size_t)bh * N_ + k0;
    float* S1 = suf1_buf + (size_t)bh * ROWS * ND;
    float* P2 = pre2_buf + (size_t)bh * ROWS * ND;

    // prefetch 16 gathers + e factors
    float gv[16], ee1[16], ee2[16];
#pragma unroll
    for (int kk = 0; kk < 16; kk++) {
        gv[kk] = gb[(size_t)sidp[kk] * OCOLS + lane];
        ee1[kk] = e1p[kk];
        ee2[kk] = e2p[kk];
    }

    // half-0 warp publishes its local sums
    if (half == 0) {
        float l1 = 0.f, l2 = 0.f;
#pragma unroll
        for (int kk = 0; kk < 16; kk++) {
            l1 = fmaf(ee1[kk], gv[kk], l1);
            l2 = fmaf(ee2[kk], gv[kk], l2);
        }
        hs1[j][lane] = l1;
        hs2[j][lane] = l2;
    }
    __syncthreads();

    float is1 = cb1_buf[((size_t)bh * 32 + c) * 32 + lane];
    float base2 = cb2_buf[((size_t)bh * 32 + c) * 32 + lane];
    float p1 = (half == 0) ? 0.f : hs1[j][lane];
    float r2 = (half == 0) ? base2 : base2 + hs2[j][lane];

    if (c == 0 && half == 0) P2[lane] = 0.f;

#pragma unroll
    for (int kk = 0; kk < 16; kk++) {
        int k = k0 + kk;
        S1[(size_t)k * ND + lane] = is1 - p1;
        p1 = fmaf(ee1[kk], gv[kk], p1);
        r2 = fmaf(ee2[kk], gv[kk], r2);
        P2[(size_t)(k + 1) * ND + lane] = r2;
    }
    if (c == 31 && half == 1) S1[(size_t)1024 * ND + lane] = 0.f;
}

// ---------------- kernel 4: output (2 independent float4 per thread) ----------------
__global__ __launch_bounds__(256) void out_k(float* __restrict__ out) {
    int idx = blockIdx.x * 256 + threadIdx.x;      // 256K threads
#pragma unroll
    for (int half = 0; half < 2; half++) {
        int e = (idx + half * 262144) << 2;        // two halves of 2M floats
        int m = e >> 8, cc = e & 255;
        int h = cc >> 5, d0 = cc & 31;
        int b = m >> 10, i = m & 1023;
        int bh = b * NH + h;
        float4 s = qscal_buf[(size_t)bh * N_ + i];
        int t = __float_as_int(s.z);
        size_t base = ((size_t)bh * ROWS + t) * ND + d0;
        float4 sf = *(const float4*)(suf1_buf + base);
        float4 pf = *(const float4*)(pre2_buf + base);
        float4 o;
        o.x = s.x * sf.x + s.y * pf.x;
        o.y = s.x * sf.y + s.y * pf.y;
        o.z = s.x * sf.z + s.y * pf.z;
        o.w = s.x * sf.w + s.y * pf.w;
        *(float4*)(out + e) = o;
    }
}

// ---------------- launcher ----------------
extern "C" void kernel_launch(void* const* d_in, const int* in_sizes, int n_in,
                              void* d_out, int out_size) {
    const float* vertex = (const float*)d_in[0];
    const float* w_vert = (const float*)d_in[1];
    const float* attn_w = (const float*)d_in[2];
    float* out = (float*)d_out;

    trans_k<<<64, 256>>>(w_vert);
    dim3 gG(2, 128);
    gemm_mma_k<<<gG, 256>>>(vertex, attn_w);
    prep_k<<<NBH, 1024>>>();
    write_k<<<dim3(8, NBH), 256>>>();
    out_k<<<M_TOT * OCOLS / 8 / 256, 256>>>(out);
}